// round 6
// baseline (speedup 1.0000x reference)
#include <cuda_runtime.h>

// 2-layer GCN: bucketed gather aggregation + f32x2 packed-FMA GEMMs.

#define N_NODES 50000
#define DIM_IN 64
#define DIM_HID 128
#define CAP 128

typedef unsigned long long u64;

__device__ __forceinline__ u64 pk(float v) {          // {v, v}
    u64 r; asm("mov.b64 %0, {%1, %1};" : "=l"(r) : "f"(v)); return r;
}
__device__ __forceinline__ void fma2(u64& d, u64 a, u64 b) {
    asm("fma.rn.f32x2 %0, %1, %2, %3;" : "=l"(d) : "l"(a), "l"(b), "l"(d));
}
__device__ __forceinline__ float2 up(u64 v) {
    float2 f; asm("mov.b64 {%0, %1}, %2;" : "=f"(f.x), "=f"(f.y) : "l"(v)); return f;
}

__device__ int   g_cnt[N_NODES];
__device__ int   g_bucket[N_NODES * CAP];
__device__ float g_dinv[N_NODES];
__device__ float g_y   [N_NODES * DIM_IN];
__device__ float g_z   [N_NODES * DIM_IN];
__device__ float g_h   [N_NODES * DIM_HID];
__device__ float g_y2  [N_NODES * DIM_IN];

// ---------------- build ----------------
__global__ void k_zero(int n) {
    int i = blockIdx.x * blockDim.x + threadIdx.x;
    if (i < n) g_cnt[i] = 0;
}
__global__ void k_place(const int* __restrict__ src, const int* __restrict__ dst, int e) {
    int i = blockIdx.x * blockDim.x + threadIdx.x;
    if (i < e) {
        int d = dst[i];
        int pos = atomicAdd(&g_cnt[d], 1);
        g_bucket[d * CAP + pos] = src[i];
    }
}

// ---------------- prescale: y = dinv*x ; materialize dinv ----------------
__global__ void k_prescale(const float* __restrict__ x, float* __restrict__ y, int n) {
    int idx = blockIdx.x * blockDim.x + threadIdx.x;  // n*16
    if (idx >= n * 16) return;
    int i = idx >> 4;
    float d = rsqrtf((float)g_cnt[i] + 1.0f);
    if ((idx & 15) == 0) g_dinv[i] = d;
    float4 v = reinterpret_cast<const float4*>(x)[idx];
    float4 o = {d * v.x, d * v.y, d * v.z, d * v.w};
    reinterpret_cast<float4*>(y)[idx] = o;
}

// ---------------- gather aggregation: 8-wide, dual accumulators ----------------
template <bool FINISH>
__global__ void k_agg(const float* __restrict__ F, float* __restrict__ O,
                      const float* __restrict__ bias, int n) {
    int node = blockIdx.x * 32 + threadIdx.y;
    if (node >= n) return;
    int lane = threadIdx.x;
    const float4* F4 = reinterpret_cast<const float4*>(F);
    const int4* cols4 = reinterpret_cast<const int4*>(g_bucket + node * CAP);
    int cnt = g_cnt[node];

    float4 acc = F4[node * 16 + lane];  // self term
    float4 acc2 = {0.f, 0.f, 0.f, 0.f};
    int j = 0;
    for (; j + 8 <= cnt; j += 8) {
        int4 ca = __ldg(&cols4[(j >> 2) + 0]);
        int4 cb = __ldg(&cols4[(j >> 2) + 1]);
        float4 u0 = F4[ca.x * 16 + lane];
        float4 u1 = F4[ca.y * 16 + lane];
        float4 u2 = F4[ca.z * 16 + lane];
        float4 u3 = F4[ca.w * 16 + lane];
        float4 u4 = F4[cb.x * 16 + lane];
        float4 u5 = F4[cb.y * 16 + lane];
        float4 u6 = F4[cb.z * 16 + lane];
        float4 u7 = F4[cb.w * 16 + lane];
        acc.x  += (u0.x + u1.x) + (u2.x + u3.x);
        acc.y  += (u0.y + u1.y) + (u2.y + u3.y);
        acc.z  += (u0.z + u1.z) + (u2.z + u3.z);
        acc.w  += (u0.w + u1.w) + (u2.w + u3.w);
        acc2.x += (u4.x + u5.x) + (u6.x + u7.x);
        acc2.y += (u4.y + u5.y) + (u6.y + u7.y);
        acc2.z += (u4.z + u5.z) + (u6.z + u7.z);
        acc2.w += (u4.w + u5.w) + (u6.w + u7.w);
    }
    for (; j + 4 <= cnt; j += 4) {
        int4 c = __ldg(&cols4[j >> 2]);
        float4 u0 = F4[c.x * 16 + lane];
        float4 u1 = F4[c.y * 16 + lane];
        float4 u2 = F4[c.z * 16 + lane];
        float4 u3 = F4[c.w * 16 + lane];
        acc.x += (u0.x + u1.x) + (u2.x + u3.x);
        acc.y += (u0.y + u1.y) + (u2.y + u3.y);
        acc.z += (u0.z + u1.z) + (u2.z + u3.z);
        acc.w += (u0.w + u1.w) + (u2.w + u3.w);
    }
    if (j < cnt) {
        int4 c = __ldg(&cols4[j >> 2]);
        int rem = cnt - j;
        float4 u0 = F4[c.x * 16 + lane];
        acc.x += u0.x; acc.y += u0.y; acc.z += u0.z; acc.w += u0.w;
        if (rem > 1) {
            float4 u1 = F4[c.y * 16 + lane];
            acc2.x += u1.x; acc2.y += u1.y; acc2.z += u1.z; acc2.w += u1.w;
        }
        if (rem > 2) {
            float4 u2 = F4[c.z * 16 + lane];
            acc.x += u2.x; acc.y += u2.y; acc.z += u2.z; acc.w += u2.w;
        }
    }
    acc.x += acc2.x; acc.y += acc2.y; acc.z += acc2.z; acc.w += acc2.w;
    float4 o;
    if (FINISH) {
        float di = g_dinv[node];
        float4 bb = reinterpret_cast<const float4*>(bias)[lane];
        o.x = fmaf(di, acc.x, bb.x);
        o.y = fmaf(di, acc.y, bb.y);
        o.z = fmaf(di, acc.z, bb.z);
        o.w = fmaf(di, acc.w, bb.w);
    } else {
        o = acc;
    }
    reinterpret_cast<float4*>(O)[node * 16 + lane] = o;
}

// ---------------- GEMM1: h = relu(b1 + dinv[r]*(z@W1))  [n,64]x[64,128] ----------------
// block (32,8): tx = 4-col group, 4 rows/thread (32 rows/block). f32x2 packed FMA.
__global__ void k_gemm1(const float* __restrict__ Z, const float* __restrict__ W,
                        const float* __restrict__ b, float* __restrict__ H, int n) {
    __shared__ float Ws[64 * 128];
    int tid = threadIdx.y * 32 + threadIdx.x;
    {
        const float4* w4 = reinterpret_cast<const float4*>(W);
        float4* s4 = reinterpret_cast<float4*>(Ws);
        for (int i = tid; i < 64 * 128 / 4; i += 256) s4[i] = w4[i];
    }
    __syncthreads();
    int tx = threadIdx.x;
    int r0 = blockIdx.x * 32 + threadIdx.y * 4;
    int rr[4];
    #pragma unroll
    for (int q = 0; q < 4; q++) rr[q] = min(r0 + q, n - 1);
    const float4* A4 = reinterpret_cast<const float4*>(Z);
    const ulonglong2* ws2 = reinterpret_cast<const ulonglong2*>(Ws);
    u64 acc[4][2] = {};
    #pragma unroll
    for (int k4 = 0; k4 < 16; k4++) {
        float4 vv0 = A4[rr[0] * 16 + k4];
        float4 vv1 = A4[rr[1] * 16 + k4];
        float4 vv2 = A4[rr[2] * 16 + k4];
        float4 vv3 = A4[rr[3] * 16 + k4];
        float va0[4] = {vv0.x, vv0.y, vv0.z, vv0.w};
        float va1[4] = {vv1.x, vv1.y, vv1.z, vv1.w};
        float va2[4] = {vv2.x, vv2.y, vv2.z, vv2.w};
        float va3[4] = {vv3.x, vv3.y, vv3.z, vv3.w};
        #pragma unroll
        for (int s = 0; s < 4; s++) {
            ulonglong2 w = ws2[(4 * k4 + s) * 32 + tx];
            u64 m0 = pk(va0[s]), m1 = pk(va1[s]), m2 = pk(va2[s]), m3 = pk(va3[s]);
            fma2(acc[0][0], m0, w.x); fma2(acc[0][1], m0, w.y);
            fma2(acc[1][0], m1, w.x); fma2(acc[1][1], m1, w.y);
            fma2(acc[2][0], m2, w.x); fma2(acc[2][1], m2, w.y);
            fma2(acc[3][0], m3, w.x); fma2(acc[3][1], m3, w.y);
        }
    }
    float4 bb = reinterpret_cast<const float4*>(b)[tx];
    float4* H4 = reinterpret_cast<float4*>(H);
    #pragma unroll
    for (int q = 0; q < 4; q++) {
        int r = r0 + q;
        if (r < n) {
            float s = g_dinv[r];
            float2 lo = up(acc[q][0]);
            float2 hi = up(acc[q][1]);
            float4 o;
            o.x = fmaxf(fmaf(s, lo.x, bb.x), 0.f);
            o.y = fmaxf(fmaf(s, lo.y, bb.y), 0.f);
            o.z = fmaxf(fmaf(s, hi.x, bb.z), 0.f);
            o.w = fmaxf(fmaf(s, hi.y, bb.w), 0.f);
            H4[(size_t)r * 32 + tx] = o;
        }
    }
}

// ---------------- GEMM2: y2 = dinv[r]*(h@W2)  [n,128]x[128,64] ----------------
// block (16,16): tx = 4-col group (64 cols), 4 rows/thread (64 rows/block). f32x2.
__global__ void k_gemm2(const float* __restrict__ H, const float* __restrict__ W,
                        float* __restrict__ Y2, int n) {
    __shared__ float Ws[128 * 64];
    int tid = threadIdx.y * 16 + threadIdx.x;
    {
        const float4* w4 = reinterpret_cast<const float4*>(W);
        float4* s4 = reinterpret_cast<float4*>(Ws);
        for (int i = tid; i < 128 * 64 / 4; i += 256) s4[i] = w4[i];
    }
    __syncthreads();
    int tx = threadIdx.x;
    int r0 = blockIdx.x * 64 + threadIdx.y * 4;
    int rr[4];
    #pragma unroll
    for (int q = 0; q < 4; q++) rr[q] = min(r0 + q, n - 1);
    const float4* A4 = reinterpret_cast<const float4*>(H);
    const ulonglong2* ws2 = reinterpret_cast<const ulonglong2*>(Ws);
    u64 acc[4][2] = {};
    #pragma unroll
    for (int k4 = 0; k4 < 32; k4++) {
        float4 vv0 = A4[rr[0] * 32 + k4];
        float4 vv1 = A4[rr[1] * 32 + k4];
        float4 vv2 = A4[rr[2] * 32 + k4];
        float4 vv3 = A4[rr[3] * 32 + k4];
        float va0[4] = {vv0.x, vv0.y, vv0.z, vv0.w};
        float va1[4] = {vv1.x, vv1.y, vv1.z, vv1.w};
        float va2[4] = {vv2.x, vv2.y, vv2.z, vv2.w};
        float va3[4] = {vv3.x, vv3.y, vv3.z, vv3.w};
        #pragma unroll
        for (int s = 0; s < 4; s++) {
            ulonglong2 w = ws2[(4 * k4 + s) * 16 + tx];
            u64 m0 = pk(va0[s]), m1 = pk(va1[s]), m2 = pk(va2[s]), m3 = pk(va3[s]);
            fma2(acc[0][0], m0, w.x); fma2(acc[0][1], m0, w.y);
            fma2(acc[1][0], m1, w.x); fma2(acc[1][1], m1, w.y);
            fma2(acc[2][0], m2, w.x); fma2(acc[2][1], m2, w.y);
            fma2(acc[3][0], m3, w.x); fma2(acc[3][1], m3, w.y);
        }
    }
    float4* Y4 = reinterpret_cast<float4*>(Y2);
    #pragma unroll
    for (int q = 0; q < 4; q++) {
        int r = r0 + q;
        if (r < n) {
            float s = g_dinv[r];
            float2 lo = up(acc[q][0]);
            float2 hi = up(acc[q][1]);
            float4 o = {s * lo.x, s * lo.y, s * hi.x, s * hi.y};
            Y4[(size_t)r * 16 + tx] = o;
        }
    }
}

extern "C" void kernel_launch(void* const* d_in, const int* in_sizes, int n_in,
                              void* d_out, int out_size) {
    const float* x  = (const float*)d_in[0];
    const int*   ei = (const int*)  d_in[1];
    const float* W1 = (const float*)d_in[2];
    const float* b1 = (const float*)d_in[3];
    const float* W2 = (const float*)d_in[4];
    const float* b2 = (const float*)d_in[5];
    float* out = (float*)d_out;

    int n = in_sizes[0] / DIM_IN;   // 50000
    int e = in_sizes[1] / 2;        // 800000
    const int* src = ei;
    const int* dst = ei + e;

    float *y, *z, *h, *y2;
    cudaGetSymbolAddress((void**)&y,  g_y);
    cudaGetSymbolAddress((void**)&z,  g_z);
    cudaGetSymbolAddress((void**)&h,  g_h);
    cudaGetSymbolAddress((void**)&y2, g_y2);

    const int TB = 256;

    // bucket build
    k_zero <<<(n + TB - 1) / TB, TB>>>(n);
    k_place<<<(e + TB - 1) / TB, TB>>>(src, dst, e);

    // layer 1
    k_prescale<<<(n * 16 + TB - 1) / TB, TB>>>(x, y, n);
    k_agg<false><<<(n + 31) / 32, dim3(16, 32)>>>(y, z, nullptr, n);
    k_gemm1<<<(n + 31) / 32, dim3(32, 8)>>>(z, W1, b1, h, n);

    // layer 2
    k_gemm2<<<(n + 63) / 64, dim3(16, 16)>>>(h, W2, y2, n);
    k_agg<true><<<(n + 31) / 32, dim3(16, 32)>>>(y2, out, b2, n);
}

// round 7
// speedup vs baseline: 1.0122x; 1.0122x over previous
#include <cuda_runtime.h>

// 2-layer GCN: warp-split gather aggregation + f32x2 packed-FMA GEMMs.
//   z_i  = dinv_i*x_i + sum dinv_c*x_c          (agg1, prescale fused)
//   h    = relu(dinv_r*(z@W1) + b1)
//   y2   = dinv_r*(h@W2)
//   out_i = dinv_i*(y2_i + sum y2_c) + b2       (agg2)

#define N_NODES 50000
#define DIM_IN 64
#define DIM_HID 128
#define CAP 128

typedef unsigned long long u64;

__device__ __forceinline__ u64 pk(float v) {
    u64 r; asm("mov.b64 %0, {%1, %1};" : "=l"(r) : "f"(v)); return r;
}
__device__ __forceinline__ void fma2(u64& d, u64 a, u64 b) {
    asm("fma.rn.f32x2 %0, %1, %2, %3;" : "=l"(d) : "l"(a), "l"(b), "l"(d));
}
__device__ __forceinline__ float2 up(u64 v) {
    float2 f; asm("mov.b64 {%0, %1}, %2;" : "=f"(f.x), "=f"(f.y) : "l"(v)); return f;
}

__device__ int   g_cnt[N_NODES];
__device__ int   g_bucket[N_NODES * CAP];
__device__ float g_dinv[N_NODES];
__device__ float g_z   [N_NODES * DIM_IN];
__device__ float g_h   [N_NODES * DIM_HID];
__device__ float g_y2  [N_NODES * DIM_IN];

// ---------------- build ----------------
__global__ void k_place(const int* __restrict__ src, const int* __restrict__ dst, int e) {
    int i = blockIdx.x * blockDim.x + threadIdx.x;
    if (i < e) {
        int d = dst[i];
        int pos = atomicAdd(&g_cnt[d], 1);
        g_bucket[d * CAP + pos] = src[i];
    }
}
__global__ void k_dinv(int n) {
    int i = blockIdx.x * blockDim.x + threadIdx.x;
    if (i < n) g_dinv[i] = rsqrtf((float)g_cnt[i] + 1.0f);
}

// ---------------- aggregation: 1 warp per node, neighbors split across warp halves --------
// lanes 0-15 = float4 slots, even chunks (+self); lanes 16-31 = same slots, odd chunks.
// Combine with shfl_down(16). PRESCALE: scale each gathered row by dinv[col].
template <bool PRESCALE, bool FINISH>
__global__ void k_agg(const float* __restrict__ F, float* __restrict__ O,
                      const float* __restrict__ bias, int n) {
    int node = blockIdx.x * 16 + (threadIdx.x >> 5);
    if (node >= n) return;
    int lane16 = threadIdx.x & 15;
    int half   = (threadIdx.x >> 4) & 1;
    const float4* F4 = reinterpret_cast<const float4*>(F);
    const int4* cols4 = reinterpret_cast<const int4*>(g_bucket + node * CAP);
    int cnt = g_cnt[node];
    float di = g_dinv[node];

    float4 acc = {0.f, 0.f, 0.f, 0.f};
    if (half == 0) {
        float4 v = F4[node * 16 + lane16];     // self term
        if (PRESCALE) { acc.x = di * v.x; acc.y = di * v.y; acc.z = di * v.z; acc.w = di * v.w; }
        else          { acc = v; }
    }
    int nchunk = (cnt + 3) >> 2;
    for (int c = half; c < nchunk; c += 2) {
        int4 cc = __ldg(&cols4[c]);
        int base = c * 4;
        // slot 0 always valid (base < cnt)
        {
            float4 u = F4[cc.x * 16 + lane16];
            if (PRESCALE) {
                float s = g_dinv[cc.x];
                acc.x = fmaf(s, u.x, acc.x); acc.y = fmaf(s, u.y, acc.y);
                acc.z = fmaf(s, u.z, acc.z); acc.w = fmaf(s, u.w, acc.w);
            } else { acc.x += u.x; acc.y += u.y; acc.z += u.z; acc.w += u.w; }
        }
        if (base + 1 < cnt) {
            float4 u = F4[cc.y * 16 + lane16];
            if (PRESCALE) {
                float s = g_dinv[cc.y];
                acc.x = fmaf(s, u.x, acc.x); acc.y = fmaf(s, u.y, acc.y);
                acc.z = fmaf(s, u.z, acc.z); acc.w = fmaf(s, u.w, acc.w);
            } else { acc.x += u.x; acc.y += u.y; acc.z += u.z; acc.w += u.w; }
        }
        if (base + 2 < cnt) {
            float4 u = F4[cc.z * 16 + lane16];
            if (PRESCALE) {
                float s = g_dinv[cc.z];
                acc.x = fmaf(s, u.x, acc.x); acc.y = fmaf(s, u.y, acc.y);
                acc.z = fmaf(s, u.z, acc.z); acc.w = fmaf(s, u.w, acc.w);
            } else { acc.x += u.x; acc.y += u.y; acc.z += u.z; acc.w += u.w; }
        }
        if (base + 3 < cnt) {
            float4 u = F4[cc.w * 16 + lane16];
            if (PRESCALE) {
                float s = g_dinv[cc.w];
                acc.x = fmaf(s, u.x, acc.x); acc.y = fmaf(s, u.y, acc.y);
                acc.z = fmaf(s, u.z, acc.z); acc.w = fmaf(s, u.w, acc.w);
            } else { acc.x += u.x; acc.y += u.y; acc.z += u.z; acc.w += u.w; }
        }
    }
    // combine the two halves
    acc.x += __shfl_down_sync(0xffffffffu, acc.x, 16);
    acc.y += __shfl_down_sync(0xffffffffu, acc.y, 16);
    acc.z += __shfl_down_sync(0xffffffffu, acc.z, 16);
    acc.w += __shfl_down_sync(0xffffffffu, acc.w, 16);
    if (half == 0) {
        float4 o;
        if (FINISH) {
            float4 bb = reinterpret_cast<const float4*>(bias)[lane16];
            o.x = fmaf(di, acc.x, bb.x);
            o.y = fmaf(di, acc.y, bb.y);
            o.z = fmaf(di, acc.z, bb.z);
            o.w = fmaf(di, acc.w, bb.w);
        } else {
            o = acc;
        }
        reinterpret_cast<float4*>(O)[node * 16 + lane16] = o;
    }
}

// ---------------- GEMM1: h = relu(b1 + dinv[r]*(z@W1))  [n,64]x[64,128], f32x2 ----------------
__global__ void k_gemm1(const float* __restrict__ Z, const float* __restrict__ W,
                        const float* __restrict__ b, float* __restrict__ H, int n) {
    __shared__ float Ws[64 * 128];
    int tid = threadIdx.y * 32 + threadIdx.x;
    {
        const float4* w4 = reinterpret_cast<const float4*>(W);
        float4* s4 = reinterpret_cast<float4*>(Ws);
        for (int i = tid; i < 64 * 128 / 4; i += 256) s4[i] = w4[i];
    }
    __syncthreads();
    int tx = threadIdx.x;
    int r0 = blockIdx.x * 32 + threadIdx.y * 4;
    int rr[4];
    #pragma unroll
    for (int q = 0; q < 4; q++) rr[q] = min(r0 + q, n - 1);
    const float4* A4 = reinterpret_cast<const float4*>(Z);
    const ulonglong2* ws2 = reinterpret_cast<const ulonglong2*>(Ws);
    u64 acc[4][2] = {};
    #pragma unroll
    for (int k4 = 0; k4 < 16; k4++) {
        float4 vv0 = A4[rr[0] * 16 + k4];
        float4 vv1 = A4[rr[1] * 16 + k4];
        float4 vv2 = A4[rr[2] * 16 + k4];
        float4 vv3 = A4[rr[3] * 16 + k4];
        float va0[4] = {vv0.x, vv0.y, vv0.z, vv0.w};
        float va1[4] = {vv1.x, vv1.y, vv1.z, vv1.w};
        float va2[4] = {vv2.x, vv2.y, vv2.z, vv2.w};
        float va3[4] = {vv3.x, vv3.y, vv3.z, vv3.w};
        #pragma unroll
        for (int s = 0; s < 4; s++) {
            ulonglong2 w = ws2[(4 * k4 + s) * 32 + tx];
            u64 m0 = pk(va0[s]), m1 = pk(va1[s]), m2 = pk(va2[s]), m3 = pk(va3[s]);
            fma2(acc[0][0], m0, w.x); fma2(acc[0][1], m0, w.y);
            fma2(acc[1][0], m1, w.x); fma2(acc[1][1], m1, w.y);
            fma2(acc[2][0], m2, w.x); fma2(acc[2][1], m2, w.y);
            fma2(acc[3][0], m3, w.x); fma2(acc[3][1], m3, w.y);
        }
    }
    float4 bb = reinterpret_cast<const float4*>(b)[tx];
    float4* H4 = reinterpret_cast<float4*>(H);
    #pragma unroll
    for (int q = 0; q < 4; q++) {
        int r = r0 + q;
        if (r < n) {
            float s = g_dinv[r];
            float2 lo = up(acc[q][0]);
            float2 hi = up(acc[q][1]);
            float4 o;
            o.x = fmaxf(fmaf(s, lo.x, bb.x), 0.f);
            o.y = fmaxf(fmaf(s, lo.y, bb.y), 0.f);
            o.z = fmaxf(fmaf(s, hi.x, bb.z), 0.f);
            o.w = fmaxf(fmaf(s, hi.y, bb.w), 0.f);
            H4[(size_t)r * 32 + tx] = o;
        }
    }
}

// ---------------- GEMM2: y2 = dinv[r]*(h@W2)  [n,128]x[128,64], f32x2 ----------------
__global__ void k_gemm2(const float* __restrict__ H, const float* __restrict__ W,
                        float* __restrict__ Y2, int n) {
    __shared__ float Ws[128 * 64];
    int tid = threadIdx.y * 16 + threadIdx.x;
    {
        const float4* w4 = reinterpret_cast<const float4*>(W);
        float4* s4 = reinterpret_cast<float4*>(Ws);
        for (int i = tid; i < 128 * 64 / 4; i += 256) s4[i] = w4[i];
    }
    __syncthreads();
    int tx = threadIdx.x;
    int r0 = blockIdx.x * 64 + threadIdx.y * 4;
    int rr[4];
    #pragma unroll
    for (int q = 0; q < 4; q++) rr[q] = min(r0 + q, n - 1);
    const float4* A4 = reinterpret_cast<const float4*>(H);
    const ulonglong2* ws2 = reinterpret_cast<const ulonglong2*>(Ws);
    u64 acc[4][2] = {};
    #pragma unroll
    for (int k4 = 0; k4 < 32; k4++) {
        float4 vv0 = A4[rr[0] * 32 + k4];
        float4 vv1 = A4[rr[1] * 32 + k4];
        float4 vv2 = A4[rr[2] * 32 + k4];
        float4 vv3 = A4[rr[3] * 32 + k4];
        float va0[4] = {vv0.x, vv0.y, vv0.z, vv0.w};
        float va1[4] = {vv1.x, vv1.y, vv1.z, vv1.w};
        float va2[4] = {vv2.x, vv2.y, vv2.z, vv2.w};
        float va3[4] = {vv3.x, vv3.y, vv3.z, vv3.w};
        #pragma unroll
        for (int s = 0; s < 4; s++) {
            ulonglong2 w = ws2[(4 * k4 + s) * 16 + tx];
            u64 m0 = pk(va0[s]), m1 = pk(va1[s]), m2 = pk(va2[s]), m3 = pk(va3[s]);
            fma2(acc[0][0], m0, w.x); fma2(acc[0][1], m0, w.y);
            fma2(acc[1][0], m1, w.x); fma2(acc[1][1], m1, w.y);
            fma2(acc[2][0], m2, w.x); fma2(acc[2][1], m2, w.y);
            fma2(acc[3][0], m3, w.x); fma2(acc[3][1], m3, w.y);
        }
    }
    float4* Y4 = reinterpret_cast<float4*>(Y2);
    #pragma unroll
    for (int q = 0; q < 4; q++) {
        int r = r0 + q;
        if (r < n) {
            float s = g_dinv[r];
            float2 lo = up(acc[q][0]);
            float2 hi = up(acc[q][1]);
            float4 o = {s * lo.x, s * lo.y, s * hi.x, s * hi.y};
            Y4[(size_t)r * 16 + tx] = o;
        }
    }
}

extern "C" void kernel_launch(void* const* d_in, const int* in_sizes, int n_in,
                              void* d_out, int out_size) {
    const float* x  = (const float*)d_in[0];
    const int*   ei = (const int*)  d_in[1];
    const float* W1 = (const float*)d_in[2];
    const float* b1 = (const float*)d_in[3];
    const float* W2 = (const float*)d_in[4];
    const float* b2 = (const float*)d_in[5];
    float* out = (float*)d_out;

    int n = in_sizes[0] / DIM_IN;   // 50000
    int e = in_sizes[1] / 2;        // 800000
    const int* src = ei;
    const int* dst = ei + e;

    float *z, *h, *y2;
    int* cnt;
    cudaGetSymbolAddress((void**)&z,   g_z);
    cudaGetSymbolAddress((void**)&h,   g_h);
    cudaGetSymbolAddress((void**)&y2,  g_y2);
    cudaGetSymbolAddress((void**)&cnt, g_cnt);

    const int TB = 256;

    // build
    cudaMemsetAsync(cnt, 0, (size_t)n * sizeof(int));
    k_place<<<(e + TB - 1) / TB, TB>>>(src, dst, e);
    k_dinv <<<(n + TB - 1) / TB, TB>>>(n);

    // layer 1
    k_agg<true, false><<<(n + 15) / 16, 512>>>(x, z, nullptr, n);
    k_gemm1<<<(n + 31) / 32, dim3(32, 8)>>>(z, W1, b1, h, n);

    // layer 2
    k_gemm2<<<(n + 63) / 64, dim3(16, 16)>>>(h, W2, y2, n);
    k_agg<false, true><<<(n + 15) / 16, 512>>>(y2, out, b2, n);
}

// round 8
// speedup vs baseline: 1.1396x; 1.1258x over previous
#include <cuda_runtime.h>

// 2-layer GCN: R5 gather aggregation + f32x2 8-row register-tiled GEMMs.

#define N_NODES 50000
#define DIM_IN 64
#define DIM_HID 128
#define CAP 128

typedef unsigned long long u64;

__device__ __forceinline__ u64 pk(float v) {
    u64 r; asm("mov.b64 %0, {%1, %1};" : "=l"(r) : "f"(v)); return r;
}
__device__ __forceinline__ void fma2(u64& d, u64 a, u64 b) {
    asm("fma.rn.f32x2 %0, %1, %2, %3;" : "=l"(d) : "l"(a), "l"(b), "l"(d));
}
__device__ __forceinline__ float2 up(u64 v) {
    float2 f; asm("mov.b64 {%0, %1}, %2;" : "=f"(f.x), "=f"(f.y) : "l"(v)); return f;
}

__device__ int   g_cnt[N_NODES];
__device__ int   g_bucket[N_NODES * CAP];
__device__ float g_dinv[N_NODES];
__device__ float g_y   [N_NODES * DIM_IN];
__device__ float g_z   [N_NODES * DIM_IN];
__device__ float g_h   [N_NODES * DIM_HID];
__device__ float g_y2  [N_NODES * DIM_IN];

// ---------------- build ----------------
__global__ void k_place(const int* __restrict__ src, const int* __restrict__ dst, int e) {
    int i = blockIdx.x * blockDim.x + threadIdx.x;
    if (i < e) {
        int d = dst[i];
        int pos = atomicAdd(&g_cnt[d], 1);
        g_bucket[d * CAP + pos] = src[i];
    }
}

// ---------------- prescale: y = dinv*x ; materialize dinv (R5) ----------------
__global__ void k_prescale(const float* __restrict__ x, float* __restrict__ y, int n) {
    int idx = blockIdx.x * blockDim.x + threadIdx.x;  // n*16
    if (idx >= n * 16) return;
    int i = idx >> 4;
    float d = rsqrtf((float)g_cnt[i] + 1.0f);
    if ((idx & 15) == 0) g_dinv[i] = d;
    float4 v = reinterpret_cast<const float4*>(x)[idx];
    float4 o = {d * v.x, d * v.y, d * v.z, d * v.w};
    reinterpret_cast<float4*>(y)[idx] = o;
}

// ---------------- gather aggregation (R5, measured 25.0us) ----------------
template <bool FINISH>
__global__ void k_agg(const float* __restrict__ F, float* __restrict__ O,
                      const float* __restrict__ bias, int n) {
    int node = blockIdx.x * 32 + threadIdx.y;
    if (node >= n) return;
    int lane = threadIdx.x;
    const float4* F4 = reinterpret_cast<const float4*>(F);
    const int4* cols4 = reinterpret_cast<const int4*>(g_bucket + node * CAP);
    int cnt = g_cnt[node];

    float4 acc = F4[node * 16 + lane];  // self term
    int j = 0;
    for (; j + 4 <= cnt; j += 4) {
        int4 c = __ldg(&cols4[j >> 2]);
        float4 u0 = F4[c.x * 16 + lane];
        float4 u1 = F4[c.y * 16 + lane];
        float4 u2 = F4[c.z * 16 + lane];
        float4 u3 = F4[c.w * 16 + lane];
        acc.x += (u0.x + u1.x) + (u2.x + u3.x);
        acc.y += (u0.y + u1.y) + (u2.y + u3.y);
        acc.z += (u0.z + u1.z) + (u2.z + u3.z);
        acc.w += (u0.w + u1.w) + (u2.w + u3.w);
    }
    if (j < cnt) {
        int4 c = __ldg(&cols4[j >> 2]);
        int rem = cnt - j;
        float4 u0 = F4[c.x * 16 + lane];
        acc.x += u0.x; acc.y += u0.y; acc.z += u0.z; acc.w += u0.w;
        if (rem > 1) {
            float4 u1 = F4[c.y * 16 + lane];
            acc.x += u1.x; acc.y += u1.y; acc.z += u1.z; acc.w += u1.w;
        }
        if (rem > 2) {
            float4 u2 = F4[c.z * 16 + lane];
            acc.x += u2.x; acc.y += u2.y; acc.z += u2.z; acc.w += u2.w;
        }
    }
    float4 o;
    if (FINISH) {
        float di = g_dinv[node];
        float4 bb = reinterpret_cast<const float4*>(bias)[lane];
        o.x = fmaf(di, acc.x, bb.x);
        o.y = fmaf(di, acc.y, bb.y);
        o.z = fmaf(di, acc.z, bb.z);
        o.w = fmaf(di, acc.w, bb.w);
    } else {
        o = acc;
    }
    reinterpret_cast<float4*>(O)[node * 16 + lane] = o;
}

// ---------------- GEMM1: h = relu(b1 + dinv[r]*(z@W1))  [n,64]x[64,128] ----------------
// block (32,8), 8 rows/thread => 64 rows/block. f32x2 FMA, 16 fma2 per LDS.128.
__global__ void __launch_bounds__(256) k_gemm1(
        const float* __restrict__ Z, const float* __restrict__ W,
        const float* __restrict__ b, float* __restrict__ H, int n) {
    __shared__ float Ws[64 * 128];
    int tid = threadIdx.y * 32 + threadIdx.x;
    {
        const float4* w4 = reinterpret_cast<const float4*>(W);
        float4* s4 = reinterpret_cast<float4*>(Ws);
        for (int i = tid; i < 64 * 128 / 4; i += 256) s4[i] = w4[i];
    }
    __syncthreads();
    int tx = threadIdx.x;
    int r0 = blockIdx.x * 64 + threadIdx.y * 8;
    int rr[8];
    #pragma unroll
    for (int q = 0; q < 8; q++) rr[q] = min(r0 + q, n - 1);
    const float4* A4 = reinterpret_cast<const float4*>(Z);
    const ulonglong2* ws2 = reinterpret_cast<const ulonglong2*>(Ws);
    u64 acc[8][2] = {};
    #pragma unroll
    for (int k4 = 0; k4 < 16; k4++) {
        float va[8][4];
        #pragma unroll
        for (int q = 0; q < 8; q++) {
            float4 v = A4[rr[q] * 16 + k4];
            va[q][0] = v.x; va[q][1] = v.y; va[q][2] = v.z; va[q][3] = v.w;
        }
        #pragma unroll
        for (int s = 0; s < 4; s++) {
            ulonglong2 w = ws2[(4 * k4 + s) * 32 + tx];
            #pragma unroll
            for (int q = 0; q < 8; q++) {
                u64 m = pk(va[q][s]);
                fma2(acc[q][0], m, w.x);
                fma2(acc[q][1], m, w.y);
            }
        }
    }
    float4 bb = reinterpret_cast<const float4*>(b)[tx];
    float4* H4 = reinterpret_cast<float4*>(H);
    #pragma unroll
    for (int q = 0; q < 8; q++) {
        int r = r0 + q;
        if (r < n) {
            float s = g_dinv[r];
            float2 lo = up(acc[q][0]);
            float2 hi = up(acc[q][1]);
            float4 o;
            o.x = fmaxf(fmaf(s, lo.x, bb.x), 0.f);
            o.y = fmaxf(fmaf(s, lo.y, bb.y), 0.f);
            o.z = fmaxf(fmaf(s, hi.x, bb.z), 0.f);
            o.w = fmaxf(fmaf(s, hi.y, bb.w), 0.f);
            H4[(size_t)r * 32 + tx] = o;
        }
    }
}

// ---------------- GEMM2: y2 = dinv[r]*(h@W2)  [n,128]x[128,64] ----------------
// block (16,16), 8 rows/thread => 128 rows/block.
__global__ void __launch_bounds__(256) k_gemm2(
        const float* __restrict__ H, const float* __restrict__ W,
        float* __restrict__ Y2, int n) {
    __shared__ float Ws[128 * 64];
    int tid = threadIdx.y * 16 + threadIdx.x;
    {
        const float4* w4 = reinterpret_cast<const float4*>(W);
        float4* s4 = reinterpret_cast<float4*>(Ws);
        for (int i = tid; i < 128 * 64 / 4; i += 256) s4[i] = w4[i];
    }
    __syncthreads();
    int tx = threadIdx.x;
    int r0 = blockIdx.x * 128 + threadIdx.y * 8;
    int rr[8];
    #pragma unroll
    for (int q = 0; q < 8; q++) rr[q] = min(r0 + q, n - 1);
    const float4* A4 = reinterpret_cast<const float4*>(H);
    const ulonglong2* ws2 = reinterpret_cast<const ulonglong2*>(Ws);
    u64 acc[8][2] = {};
    #pragma unroll
    for (int k4 = 0; k4 < 32; k4++) {
        float va[8][4];
        #pragma unroll
        for (int q = 0; q < 8; q++) {
            float4 v = A4[rr[q] * 32 + k4];
            va[q][0] = v.x; va[q][1] = v.y; va[q][2] = v.z; va[q][3] = v.w;
        }
        #pragma unroll
        for (int s = 0; s < 4; s++) {
            ulonglong2 w = ws2[(4 * k4 + s) * 16 + tx];
            #pragma unroll
            for (int q = 0; q < 8; q++) {
                u64 m = pk(va[q][s]);
                fma2(acc[q][0], m, w.x);
                fma2(acc[q][1], m, w.y);
            }
        }
    }
    float4* Y4 = reinterpret_cast<float4*>(Y2);
    #pragma unroll
    for (int q = 0; q < 8; q++) {
        int r = r0 + q;
        if (r < n) {
            float s = g_dinv[r];
            float2 lo = up(acc[q][0]);
            float2 hi = up(acc[q][1]);
            float4 o = {s * lo.x, s * lo.y, s * hi.x, s * hi.y};
            Y4[(size_t)r * 16 + tx] = o;
        }
    }
}

extern "C" void kernel_launch(void* const* d_in, const int* in_sizes, int n_in,
                              void* d_out, int out_size) {
    const float* x  = (const float*)d_in[0];
    const int*   ei = (const int*)  d_in[1];
    const float* W1 = (const float*)d_in[2];
    const float* b1 = (const float*)d_in[3];
    const float* W2 = (const float*)d_in[4];
    const float* b2 = (const float*)d_in[5];
    float* out = (float*)d_out;

    int n = in_sizes[0] / DIM_IN;   // 50000
    int e = in_sizes[1] / 2;        // 800000
    const int* src = ei;
    const int* dst = ei + e;

    float *y, *z, *h, *y2;
    int* cnt;
    cudaGetSymbolAddress((void**)&y,   g_y);
    cudaGetSymbolAddress((void**)&z,   g_z);
    cudaGetSymbolAddress((void**)&h,   g_h);
    cudaGetSymbolAddress((void**)&y2,  g_y2);
    cudaGetSymbolAddress((void**)&cnt, g_cnt);

    const int TB = 256;

    // build
    cudaMemsetAsync(cnt, 0, (size_t)n * sizeof(int));
    k_place<<<(e + TB - 1) / TB, TB>>>(src, dst, e);

    // layer 1
    k_prescale<<<(n * 16 + TB - 1) / TB, TB>>>(x, y, n);
    k_agg<false><<<(n + 31) / 32, dim3(16, 32)>>>(y, z, nullptr, n);
    k_gemm1<<<(n + 63) / 64, dim3(32, 8)>>>(z, W1, b1, h, n);

    // layer 2
    k_gemm2<<<(n + 127) / 128, dim3(16, 16)>>>(h, W2, y2, n);
    k_agg<true><<<(n + 31) / 32, dim3(16, 32)>>>(y2, out, b2, n);
}